// round 2
// baseline (speedup 1.0000x reference)
#include <cuda_runtime.h>

#define NJ   17
#define NP   14
#define NB   256
#define NCH  59            // 17 + 3*14
#define GX   (NJ + NP)     // 31 block columns
#define NBLK (GX * NB)     // 7936 total blocks

__constant__ int c_par[NP] = {0,1,2,0,4,5,0,8,14,15,8,11,12,8};
__constant__ int c_chi[NP] = {1,2,3,4,5,6,8,14,15,16,11,12,13,10};

// Per-block partial results (every slot written every launch -> no pre-zeroing).
__device__ float        g_part[NBLK];
__device__ unsigned int g_count;   // zero at module load; last block resets each call

// max of exp(-(i-x)^2/4) over integer grid i in [0,63]: attained at nearest grid point.
__device__ __forceinline__ float gmax1d(float x) {
    float i = fminf(fmaxf(rintf(x), 0.f), 63.f);
    float d = i - x;
    return __expf(-d * d * 0.25f);
}

__global__ void __launch_bounds__(256)
k_fused(const float* __restrict__ mo,
        const float* __restrict__ joints,
        const float* __restrict__ j2d,
        const float* __restrict__ pred,
        float* __restrict__ out) {
    __shared__ float ex[64], ey[64], ex2[64], ey2[64];
    __shared__ float red[8];
    __shared__ int   s_last;

    const int b    = blockIdx.y;
    const int tid  = threadIdx.x;
    const int lbid = b * GX + blockIdx.x;

    float partial;   // this block's contribution to (L2D_sum + LHEM_sum)

    if (blockIdx.x < NJ) {
        // ---------------- L2D path ----------------
        const int j = blockIdx.x;
        const float x = j2d[(b * NJ + j) * 2 + 0] * 64.f;
        const float y = j2d[(b * NJ + j) * 2 + 1] * 64.f;
        const float inv = 1.f / (gmax1d(x) * gmax1d(y));
        if (tid < 64)       { float d = (float)tid - x;        ex[tid] = expf(-d * d * 0.25f) * inv; }
        else if (tid < 128) { int k = tid - 64; float d = (float)k - y; ey[k] = expf(-d * d * 0.25f); }
        __syncthreads();

        const float4* p = (const float4*)(mo + (((size_t)b * NCH + j) << 12));
        float acc = 0.f;
        #pragma unroll
        for (int it = 0; it < 4; it++) {
            int e4 = tid + it * 256;
            float4 m = p[e4];
            int e = e4 << 2;
            int i = e >> 6, k = e & 63;
            float hx = ex[i];
            float d0 = m.x - hx * ey[k + 0];
            float d1 = m.y - hx * ey[k + 1];
            float d2 = m.z - hx * ey[k + 2];
            float d3 = m.w - hx * ey[k + 3];
            acc += d0 * d0 + d1 * d1 + d2 * d2 + d3 * d3;
        }
        // block reduce
        #pragma unroll
        for (int o = 16; o > 0; o >>= 1) acc += __shfl_down_sync(0xffffffffu, acc, o);
        if ((tid & 31) == 0) red[tid >> 5] = acc;
        __syncthreads();
        if (tid < 32) {
            acc = (tid < 8) ? red[tid] : 0.f;
            #pragma unroll
            for (int o = 4; o > 0; o >>= 1) acc += __shfl_down_sync(0xffffffffu, acc, o);
        }
        partial = acc;
    } else {
        // ---------------- HEM path ----------------
        const int pr = blockIdx.x - NJ;
        const int pj = c_par[pr], cj = c_chi[pr];
        const float xp = j2d[(b * NJ + pj) * 2 + 0] * 64.f;
        const float yp = j2d[(b * NJ + pj) * 2 + 1] * 64.f;
        const float xc = j2d[(b * NJ + cj) * 2 + 0] * 64.f;
        const float yc = j2d[(b * NJ + cj) * 2 + 1] * 64.f;
        const float invp = 1.f / (gmax1d(xp) * gmax1d(yp));
        const float invc = 1.f / (gmax1d(xc) * gmax1d(yc));
        if (tid < 64)       { float d = (float)tid - xp;         ex [tid] = expf(-d * d * 0.25f) * invp; }
        else if (tid < 128) { int k = tid - 64;  float d = (float)k - yp; ey [k] = expf(-d * d * 0.25f); }
        else if (tid < 192) { int k = tid - 128; float d = (float)k - xc; ex2[k] = expf(-d * d * 0.25f) * invc; }
        else                { int k = tid - 192; float d = (float)k - yc; ey2[k] = expf(-d * d * 0.25f); }
        __syncthreads();

        const float dz = joints[(b * NJ + pj) * 3 + 2] - joints[(b * NJ + cj) * 3 + 2];
        const int r = (dz > 0.1f) ? 1 : ((fabsf(dz) < 0.1f) ? 0 : -1);

        const float4* p0 = (const float4*)(mo + (((size_t)b * NCH + NJ + pr * 3) << 12));
        float a0 = 0.f, a1 = 0.f, a2 = 0.f;
        #pragma unroll
        for (int it = 0; it < 4; it++) {
            int e4 = tid + it * 256;
            int e  = e4 << 2;
            int i  = e >> 6, k = e & 63;
            float hpx = ex[i];
            float hcx = ex2[i];
            float m0[4], m1[4], m2[4];
            *(float4*)m0 = p0[e4];
            *(float4*)m1 = p0[e4 + 1024];
            *(float4*)m2 = p0[e4 + 2048];
            #pragma unroll
            for (int n = 0; n < 4; n++) {
                float hp = hpx * ey[k + n];
                float hc = hcx * ey2[k + n];
                float t0 = (r == -1) ? hc : 0.f;
                float t1 = (r ==  0) ? (hp + hc) : hp;
                float t2 = (r ==  1) ? hc : 0.f;
                float d0 = t0 - m0[n];
                float d1 = t1 - m1[n];
                float d2 = t2 - m2[n];
                a0 += d0 * d0;
                a1 += d1 * d1;
                a2 += d2 * d2;
            }
        }
        // three block reduces (serialized through red[])
        float S0, S1, S2;
        {
            float v = a0;
            #pragma unroll
            for (int o = 16; o > 0; o >>= 1) v += __shfl_down_sync(0xffffffffu, v, o);
            if ((tid & 31) == 0) red[tid >> 5] = v;
            __syncthreads();
            v = (tid < 8) ? red[tid] : 0.f;
            if (tid < 32) {
                #pragma unroll
                for (int o = 4; o > 0; o >>= 1) v += __shfl_down_sync(0xffffffffu, v, o);
            }
            S0 = v;
            __syncthreads();
        }
        {
            float v = a1;
            #pragma unroll
            for (int o = 16; o > 0; o >>= 1) v += __shfl_down_sync(0xffffffffu, v, o);
            if ((tid & 31) == 0) red[tid >> 5] = v;
            __syncthreads();
            v = (tid < 8) ? red[tid] : 0.f;
            if (tid < 32) {
                #pragma unroll
                for (int o = 4; o > 0; o >>= 1) v += __shfl_down_sync(0xffffffffu, v, o);
            }
            S1 = v;
            __syncthreads();
        }
        {
            float v = a2;
            #pragma unroll
            for (int o = 16; o > 0; o >>= 1) v += __shfl_down_sync(0xffffffffu, v, o);
            if ((tid & 31) == 0) red[tid >> 5] = v;
            __syncthreads();
            v = (tid < 8) ? red[tid] : 0.f;
            if (tid < 32) {
                #pragma unroll
                for (int o = 4; o > 0; o >>= 1) v += __shfl_down_sync(0xffffffffu, v, o);
            }
            S2 = v;
        }
        if (tid == 0) {
            float s = sqrtf(S0) + sqrtf(S1) + sqrtf(S2);
            partial = s * s;
        }
    }

    // ---- publish partial, detect last block ----
    if (tid == 0) {
        g_part[lbid] = partial;
        __threadfence();
        unsigned int prev = atomicAdd(&g_count, 1u);
        s_last = (prev == (unsigned)(NBLK - 1)) ? 1 : 0;
    }
    __syncthreads();
    if (!s_last) return;

    // ---- last block: final reduction + l3d + output ----
    __shared__ double dsh[256];
    double s = 0.0;
    for (int i = tid; i < NBLK; i += 256) s += (double)g_part[i];

    // l3d: thread tid handles batch tid (51 elements)
    double l = 0.0;
    const float* jb = joints + tid * NJ * 3;
    const float* pb = pred   + tid * NJ * 3;
    #pragma unroll
    for (int i = 0; i < NJ * 3; i++) l += fabs((double)jb[i] - (double)pb[i]);

    dsh[tid] = l + 0.005 * s;
    __syncthreads();
    #pragma unroll
    for (int o = 128; o > 0; o >>= 1) {
        if (tid < o) dsh[tid] += dsh[tid + o];
        __syncthreads();
    }
    if (tid == 0) {
        out[0] = (float)(dsh[0] / 256.0);
        g_count = 0;   // reset for next (graph-replayed) launch
    }
}

extern "C" void kernel_launch(void* const* d_in, const int* in_sizes, int n_in,
                              void* d_out, int out_size) {
    const float* pred   = (const float*)d_in[0];
    const float* joints = (const float*)d_in[1];
    const float* mo     = (const float*)d_in[2];
    const float* j2d    = (const float*)d_in[3];
    float* out = (float*)d_out;

    k_fused<<<dim3(GX, NB), 256>>>(mo, joints, j2d, pred, out);
}

// round 3
// speedup vs baseline: 1.2589x; 1.2589x over previous
#include <cuda_runtime.h>

#define NJ   17
#define NP   14
#define NB   256
#define NCH  59            // 17 + 3*14
#define GX   (NJ + NP)     // 31 block columns
#define NBLK (GX * NB)     // 7936 total blocks

__constant__ int c_par[NP] = {0,1,2,0,4,5,0,8,14,15,8,11,12,8};
__constant__ int c_chi[NP] = {1,2,3,4,5,6,8,14,15,16,11,12,13,10};

// Per-block partial results (every slot written every launch -> no pre-zeroing).
__device__ float        g_part[NBLK];
__device__ unsigned int g_count;   // zero at module load; last block resets each call

// max of exp(-(i-x)^2/4) over integer grid i in [0,63]: attained at nearest grid point.
__device__ __forceinline__ float gmax1d(float x) {
    float i = fminf(fmaxf(rintf(x), 0.f), 63.f);
    float d = i - x;
    return __expf(-d * d * 0.25f);
}

__device__ __forceinline__ float blockReduce256(float v, float* red, int tid) {
    #pragma unroll
    for (int o = 16; o > 0; o >>= 1) v += __shfl_down_sync(0xffffffffu, v, o);
    if ((tid & 31) == 0) red[tid >> 5] = v;
    __syncthreads();
    v = (tid < 8) ? red[tid] : 0.f;
    if (tid < 32) {
        #pragma unroll
        for (int o = 4; o > 0; o >>= 1) v += __shfl_down_sync(0xffffffffu, v, o);
    }
    return v;   // valid on tid 0
}

__global__ void __launch_bounds__(256, 8)
k_fused(const float* __restrict__ mo,
        const float* __restrict__ joints,
        const float* __restrict__ j2d,
        const float* __restrict__ pred,
        float* __restrict__ out) {
    __shared__ float ex[64], ey[64], ex2[64], ey2[64];
    __shared__ float red[8];
    __shared__ int   s_last;

    const int b    = blockIdx.y;
    const int tid  = threadIdx.x;
    const int lbid = b * GX + blockIdx.x;

    float partial = 0.f;   // this block's contribution to (L2D_sum + LHEM_sum), tid 0

    if (blockIdx.x < NJ) {
        // ---------------- L2D path ----------------
        const int j = blockIdx.x;
        const float x = j2d[(b * NJ + j) * 2 + 0] * 64.f;
        const float y = j2d[(b * NJ + j) * 2 + 1] * 64.f;
        const float inv = 1.f / (gmax1d(x) * gmax1d(y));
        if (tid < 64)       { float d = (float)tid - x;        ex[tid] = expf(-d * d * 0.25f) * inv; }
        else if (tid < 128) { int k = tid - 64; float d = (float)k - y; ey[k] = expf(-d * d * 0.25f); }
        __syncthreads();

        const float4* p = (const float4*)(mo + (((size_t)b * NCH + j) << 12));
        float acc = 0.f;
        #pragma unroll
        for (int it = 0; it < 4; it++) {
            int e4 = tid + it * 256;
            float4 m = p[e4];
            int e = e4 << 2;
            int i = e >> 6, k = e & 63;
            float hx = ex[i];
            float d0 = m.x - hx * ey[k + 0];
            float d1 = m.y - hx * ey[k + 1];
            float d2 = m.z - hx * ey[k + 2];
            float d3 = m.w - hx * ey[k + 3];
            acc += d0 * d0 + d1 * d1 + d2 * d2 + d3 * d3;
        }
        partial = blockReduce256(acc, red, tid);
    } else {
        // ---------------- HEM path ----------------
        const int pr = blockIdx.x - NJ;
        const int pj = c_par[pr], cj = c_chi[pr];
        const float xp = j2d[(b * NJ + pj) * 2 + 0] * 64.f;
        const float yp = j2d[(b * NJ + pj) * 2 + 1] * 64.f;
        const float xc = j2d[(b * NJ + cj) * 2 + 0] * 64.f;
        const float yc = j2d[(b * NJ + cj) * 2 + 1] * 64.f;
        const float invp = 1.f / (gmax1d(xp) * gmax1d(yp));
        const float invc = 1.f / (gmax1d(xc) * gmax1d(yc));
        if (tid < 64)       { float d = (float)tid - xp;         ex [tid] = expf(-d * d * 0.25f) * invp; }
        else if (tid < 128) { int k = tid - 64;  float d = (float)k - yp; ey [k] = expf(-d * d * 0.25f); }
        else if (tid < 192) { int k = tid - 128; float d = (float)k - xc; ex2[k] = expf(-d * d * 0.25f) * invc; }
        else                { int k = tid - 192; float d = (float)k - yc; ey2[k] = expf(-d * d * 0.25f); }
        __syncthreads();

        const float dz = joints[(b * NJ + pj) * 3 + 2] - joints[(b * NJ + cj) * 3 + 2];
        const int r = (dz > 0.1f) ? 1 : ((fabsf(dz) < 0.1f) ? 0 : -1);

        const float4* p0 = (const float4*)(mo + (((size_t)b * NCH + NJ + pr * 3) << 12));
        float a0 = 0.f, a1 = 0.f, a2 = 0.f;
        #pragma unroll
        for (int it = 0; it < 4; it++) {
            int e4 = tid + it * 256;
            int e  = e4 << 2;
            int i  = e >> 6, k = e & 63;
            float hpx = ex[i];
            float hcx = ex2[i];
            float m0[4], m1[4], m2[4];
            *(float4*)m0 = p0[e4];
            *(float4*)m1 = p0[e4 + 1024];
            *(float4*)m2 = p0[e4 + 2048];
            #pragma unroll
            for (int n = 0; n < 4; n++) {
                float hp = hpx * ey[k + n];
                float hc = hcx * ey2[k + n];
                float t0 = (r == -1) ? hc : 0.f;
                float t1 = (r ==  0) ? (hp + hc) : hp;
                float t2 = (r ==  1) ? hc : 0.f;
                float d0 = t0 - m0[n];
                float d1 = t1 - m1[n];
                float d2 = t2 - m2[n];
                a0 += d0 * d0;
                a1 += d1 * d1;
                a2 += d2 * d2;
            }
        }
        float S0 = blockReduce256(a0, red, tid);
        __syncthreads();
        float S1 = blockReduce256(a1, red, tid);
        __syncthreads();
        float S2 = blockReduce256(a2, red, tid);
        if (tid == 0) {
            float s = sqrtf(S0) + sqrtf(S1) + sqrtf(S2);
            partial = s * s;
        }
    }

    // ---- publish partial, detect last block ----
    if (tid == 0) {
        g_part[lbid] = partial;
        __threadfence();
        unsigned int prev = atomicAdd(&g_count, 1u);
        s_last = (prev == (unsigned)(NBLK - 1)) ? 1 : 0;
    }
    __syncthreads();
    if (!s_last) return;

    // ---- last block: final reduction (float, positive terms) + l3d + output ----
    float s = 0.f;
    for (int i = tid; i < NBLK; i += 256) s += __ldcg(&g_part[i]);

    // l3d: thread tid handles batch tid (51 abs-diffs)
    float l = 0.f;
    const float* jb = joints + tid * NJ * 3;
    const float* pb = pred   + tid * NJ * 3;
    #pragma unroll
    for (int i = 0; i < NJ * 3; i++) l += fabsf(jb[i] - pb[i]);

    float v = l + 0.005f * s;
    __syncthreads();   // red[] reuse
    float tot = blockReduce256(v, red, tid);
    if (tid == 0) {
        out[0] = tot * (1.f / 256.f);
        g_count = 0;   // reset for next (graph-replayed) launch
    }
}

extern "C" void kernel_launch(void* const* d_in, const int* in_sizes, int n_in,
                              void* d_out, int out_size) {
    const float* pred   = (const float*)d_in[0];
    const float* joints = (const float*)d_in[1];
    const float* mo     = (const float*)d_in[2];
    const float* j2d    = (const float*)d_in[3];
    float* out = (float*)d_out;

    k_fused<<<dim3(GX, NB), 256>>>(mo, joints, j2d, pred, out);
}